// round 6
// baseline (speedup 1.0000x reference)
#include <cuda_runtime.h>
#include <cstdint>

#define N_NODES 100000
#define N_EDGES 1000000
#define D 64
#define CAP 64           // padded CSR slots/node (Poisson(10): P(deg>64)~1e-30; inline fallback exists)

// Scratch (device globals — no allocations allowed)
__device__ int g_cnt[N_NODES];
__device__ __align__(16) int g_csr[N_NODES * CAP];

// ---------------------------------------------------------------------------
// Kernel 1: zero degree counters
// ---------------------------------------------------------------------------
__global__ __launch_bounds__(256) void zero_kernel() {
    const int stride = gridDim.x * blockDim.x;
    for (int idx = blockIdx.x * blockDim.x + threadIdx.x; idx < N_NODES; idx += stride)
        g_cnt[idx] = 0;
}

// ---------------------------------------------------------------------------
// Kernel 2: CSR fill. pos = atomicAdd(cnt[dst]); csr[dst*CAP+pos] = src.
// Overflow edges (pos >= CAP) are simply counted via cnt; the fused kernel
// detects cnt > CAP and rescans the edge list for that node.
// ---------------------------------------------------------------------------
__global__ __launch_bounds__(256) void fill_kernel(const int* __restrict__ ei) {
    const int e = blockIdx.x * 256 + threadIdx.x;
    if (e >= N_EDGES) return;
    const int dst = __ldg(ei + N_EDGES + e);
    const int src = __ldg(ei + e);
    const int pos = atomicAdd(g_cnt + dst, 1);
    if (pos < CAP) g_csr[dst * CAP + pos] = src;
}

// ---------------------------------------------------------------------------
// Kernel 3 (fused): per block of 128 nodes:
//   phase A: stage W_l/W_r (k-major) + bias in smem
//   phase B: 16 half-warps gather neighbor means from CSR straight into smem
//            (register float4 accumulation, LDG.128, zero atomics), plus x tile
//   phase C: register-tiled GEMM with packed fma.rn.f32x2, bias + ReLU epilogue
// ---------------------------------------------------------------------------
#define WPAD 68      // 64 + 4 floats
#define APAD 132     // 128 + 4 floats

__global__ __launch_bounds__(256) void fused_kernel(
    const float* __restrict__ x,
    const int*   __restrict__ ei,
    const float* __restrict__ Wl,
    const float* __restrict__ bl,
    const float* __restrict__ Wr,
    float* __restrict__ out)
{
    extern __shared__ float sm[];
    float* sWl = sm;                        // [64][WPAD] k-major
    float* sWr = sWl + D * WPAD;            // [64][WPAD]
    float* sA  = sWr + D * WPAD;            // [64][APAD] mean, k-major
    float* sX  = sA  + D * APAD;            // [64][APAD] x, k-major
    float* sB  = sX  + D * APAD;            // [64]

    const int tid = threadIdx.x;
    const int node0 = blockIdx.x * 128;

    // --- phase A: weights + bias ---
    for (int t = tid; t < 1024; t += 256) {
        const int o = t >> 4, k = (t & 15) * 4;
        float4 w = __ldg(reinterpret_cast<const float4*>(Wl) + t);
        sWl[(k+0)*WPAD+o]=w.x; sWl[(k+1)*WPAD+o]=w.y;
        sWl[(k+2)*WPAD+o]=w.z; sWl[(k+3)*WPAD+o]=w.w;
        float4 u = __ldg(reinterpret_cast<const float4*>(Wr) + t);
        sWr[(k+0)*WPAD+o]=u.x; sWr[(k+1)*WPAD+o]=u.y;
        sWr[(k+2)*WPAD+o]=u.z; sWr[(k+3)*WPAD+o]=u.w;
    }
    if (tid < D) sB[tid] = __ldg(bl + tid);

    // --- phase B: CSR gather of mean tile + x tile (half-warp per node) ---
    const int hw = tid >> 4;                // half-warp id 0..15
    const int j  = tid & 15;                // float4 slot within the 64-dim row
    const float4* x4 = reinterpret_cast<const float4*>(x);

    #pragma unroll 1
    for (int rnd = 0; rnd < 8; rnd++) {
        const int node = node0 + rnd * 16 + hw;
        float4 acc = make_float4(0.f, 0.f, 0.f, 0.f);
        float4 xv  = acc;
        float r = 0.f;
        if (node < N_NODES) {
            const int cnt = g_cnt[node];
            r = 1.0f / (float)(cnt > 1 ? cnt : 1);
            xv = __ldg(x4 + (size_t)node * 16 + j);
            if (cnt <= CAP) {
                const int4* row = reinterpret_cast<const int4*>(g_csr + node * CAP);
                for (int e0 = 0; e0 < cnt; e0 += 4) {
                    int4 s = __ldg(row + (e0 >> 2));         // broadcast in half-warp
                    const int rem = cnt - e0;
                    float4 v0 = __ldg(x4 + (size_t)s.x * 16 + j);
                    float4 v1, v2, v3;
                    if (rem > 1) v1 = __ldg(x4 + (size_t)s.y * 16 + j);
                    if (rem > 2) v2 = __ldg(x4 + (size_t)s.z * 16 + j);
                    if (rem > 3) v3 = __ldg(x4 + (size_t)s.w * 16 + j);
                    acc.x += v0.x; acc.y += v0.y; acc.z += v0.z; acc.w += v0.w;
                    if (rem > 1) { acc.x += v1.x; acc.y += v1.y; acc.z += v1.z; acc.w += v1.w; }
                    if (rem > 2) { acc.x += v2.x; acc.y += v2.y; acc.z += v2.z; acc.w += v2.w; }
                    if (rem > 3) { acc.x += v3.x; acc.y += v3.y; acc.z += v3.z; acc.w += v3.w; }
                }
            } else {
                // overflow fallback (~never): rescan full edge list for this node
                for (int e = 0; e < N_EDGES; e++) {
                    if (__ldg(ei + N_EDGES + e) == node) {
                        float4 v = __ldg(x4 + (size_t)__ldg(ei + e) * 16 + j);
                        acc.x += v.x; acc.y += v.y; acc.z += v.z; acc.w += v.w;
                    }
                }
            }
        }
        const int k = j * 4;
        sA[(k+0)*APAD+node0%1 + (rnd*16+hw)] = acc.x * r;   // see below: linearized
        sA[(k+1)*APAD+(rnd*16+hw)] = acc.y * r;
        sA[(k+2)*APAD+(rnd*16+hw)] = acc.z * r;
        sA[(k+3)*APAD+(rnd*16+hw)] = acc.w * r;
        sX[(k+0)*APAD+(rnd*16+hw)] = xv.x;
        sX[(k+1)*APAD+(rnd*16+hw)] = xv.y;
        sX[(k+2)*APAD+(rnd*16+hw)] = xv.z;
        sX[(k+3)*APAD+(rnd*16+hw)] = xv.w;
    }
    __syncthreads();

    // --- phase C: GEMM ---
    const int tx = tid & 15;
    const int ty = tid >> 4;
    const int nb = ty * 8;
    const int ob = tx * 4;

    unsigned long long acc2[4][4];
    #pragma unroll
    for (int o = 0; o < 4; o++) {
        const float b = sB[ob + o];
        unsigned long long bp;
        asm("mov.b64 %0, {%1, %2};" : "=l"(bp) : "f"(b), "f"(b));
        #pragma unroll
        for (int m = 0; m < 4; m++) acc2[m][o] = bp;
    }

    #pragma unroll 8
    for (int k = 0; k < D; k++) {
        const float4 wl4 = *reinterpret_cast<const float4*>(sWl + k*WPAD + ob);
        const float4 wr4 = *reinterpret_cast<const float4*>(sWr + k*WPAD + ob);
        const ulonglong2 aA = *reinterpret_cast<const ulonglong2*>(sA + k*APAD + nb);
        const ulonglong2 aB = *reinterpret_cast<const ulonglong2*>(sA + k*APAD + nb + 4);
        const ulonglong2 xA = *reinterpret_cast<const ulonglong2*>(sX + k*APAD + nb);
        const ulonglong2 xB = *reinterpret_cast<const ulonglong2*>(sX + k*APAD + nb + 4);
        const unsigned long long ap[4] = {aA.x, aA.y, aB.x, aB.y};
        const unsigned long long xp[4] = {xA.x, xA.y, xB.x, xB.y};
        const float wlv[4] = {wl4.x, wl4.y, wl4.z, wl4.w};
        const float wrv[4] = {wr4.x, wr4.y, wr4.z, wr4.w};
        #pragma unroll
        for (int o = 0; o < 4; o++) {
            unsigned long long wl2, wr2;
            asm("mov.b64 %0, {%1, %2};" : "=l"(wl2) : "f"(wlv[o]), "f"(wlv[o]));
            asm("mov.b64 %0, {%1, %2};" : "=l"(wr2) : "f"(wrv[o]), "f"(wrv[o]));
            #pragma unroll
            for (int m = 0; m < 4; m++) {
                asm("fma.rn.f32x2 %0, %1, %2, %0;" : "+l"(acc2[m][o]) : "l"(ap[m]), "l"(wl2));
                asm("fma.rn.f32x2 %0, %1, %2, %0;" : "+l"(acc2[m][o]) : "l"(xp[m]), "l"(wr2));
            }
        }
    }

    // --- epilogue: ReLU + store ---
    #pragma unroll
    for (int m = 0; m < 4; m++) {
        float lo[4], hi[4];
        #pragma unroll
        for (int o = 0; o < 4; o++)
            asm("mov.b64 {%0, %1}, %2;" : "=f"(lo[o]), "=f"(hi[o]) : "l"(acc2[m][o]));
        const int g0 = node0 + nb + m * 2;
        if (g0 < N_NODES) {
            float4 v = make_float4(fmaxf(lo[0],0.f), fmaxf(lo[1],0.f),
                                   fmaxf(lo[2],0.f), fmaxf(lo[3],0.f));
            *reinterpret_cast<float4*>(out + (size_t)g0*D + ob) = v;
        }
        if (g0 + 1 < N_NODES) {
            float4 v = make_float4(fmaxf(hi[0],0.f), fmaxf(hi[1],0.f),
                                   fmaxf(hi[2],0.f), fmaxf(hi[3],0.f));
            *reinterpret_cast<float4*>(out + (size_t)(g0+1)*D + ob) = v;
        }
    }
}

// ---------------------------------------------------------------------------
extern "C" void kernel_launch(void* const* d_in, const int* in_sizes, int n_in,
                              void* d_out, int out_size)
{
    const float* x  = (const float*)d_in[0];
    const int*   ei = (const int*)d_in[1];     // int32 (JAX x64 disabled)
    const float* Wl = (const float*)d_in[2];
    const float* bl = (const float*)d_in[3];
    const float* Wr = (const float*)d_in[4];
    float* out = (float*)d_out;

    const int smem_bytes = (2 * D * WPAD + 2 * D * APAD + D) * sizeof(float);
    cudaFuncSetAttribute(fused_kernel, cudaFuncAttributeMaxDynamicSharedMemorySize, smem_bytes);

    zero_kernel<<<98, 256>>>();
    fill_kernel<<<(N_EDGES + 255) / 256, 256>>>(ei);
    fused_kernel<<<(N_NODES + 127) / 128, 256, smem_bytes>>>(x, ei, Wl, bl, Wr, out);
}

// round 8
// speedup vs baseline: 1.0408x; 1.0408x over previous
#include <cuda_runtime.h>
#include <cstdint>

#define N_NODES 100000
#define N_EDGES 1000000
#define D 64
#define CAP 64           // padded CSR slots/node (Poisson(10): P(deg>64)~1e-30; inline fallback exists)

// Scratch (device globals — no allocations allowed)
__device__ __align__(16) float g_mean[N_NODES * D];
__device__ int g_cnt[N_NODES];
__device__ __align__(16) int g_csr[N_NODES * CAP];

// ---------------------------------------------------------------------------
// Kernel 1: zero degree counters
// ---------------------------------------------------------------------------
__global__ __launch_bounds__(256) void zero_kernel() {
    const int i = blockIdx.x * 256 + threadIdx.x;
    if (i < N_NODES) g_cnt[i] = 0;
}

// ---------------------------------------------------------------------------
// Kernel 2: CSR fill, 2 edges/thread (int2 loads). Overflow just counts.
// ---------------------------------------------------------------------------
__global__ __launch_bounds__(256) void fill_kernel(const int* __restrict__ ei) {
    const int t = blockIdx.x * 256 + threadIdx.x;
    if (t >= N_EDGES / 2) return;                 // tail guard (round-7 bug fix)
    const int2 src2 = __ldg(reinterpret_cast<const int2*>(ei) + t);
    const int2 dst2 = __ldg(reinterpret_cast<const int2*>(ei + N_EDGES) + t);
    int pos = atomicAdd(g_cnt + dst2.x, 1);
    if (pos < CAP) g_csr[dst2.x * CAP + pos] = src2.x;
    pos = atomicAdd(g_cnt + dst2.y, 1);
    if (pos < CAP) g_csr[dst2.y * CAP + pos] = src2.y;
}

// ---------------------------------------------------------------------------
// Kernel 3: gather. Half-warp (16 lanes) per node: stream neighbor rows with
// LDG.128, accumulate in registers, write mean row once. No float atomics.
// Next edge-id int4 is prefetched to keep MLP up across iterations.
// Overflow fallback (never taken in practice): rescan the edge list inline.
// ---------------------------------------------------------------------------
__global__ __launch_bounds__(256) void gather_kernel(const float* __restrict__ x,
                                                     const int* __restrict__ ei) {
    const int warp = blockIdx.x * 8 + (threadIdx.x >> 5);
    const int lane = threadIdx.x & 31;
    const int sub  = lane >> 4;
    const int j    = lane & 15;           // float4 slot in the 64-dim row
    const int node = warp * 2 + sub;      // grid covers exactly N_NODES

    const int cnt  = g_cnt[node];
    const float r  = 1.0f / (float)(cnt > 1 ? cnt : 1);
    const float4* x4 = reinterpret_cast<const float4*>(x);

    float4 acc = make_float4(0.f, 0.f, 0.f, 0.f);
    if (cnt <= CAP) {
        const int4* row = reinterpret_cast<const int4*>(g_csr + node * CAP);
        int4 s = __ldg(row);                     // broadcast within half-warp
        for (int e0 = 0; e0 < cnt; e0 += 4) {
            const int4 cur = s;
            if (e0 + 4 < cnt) s = __ldg(row + (e0 >> 2) + 1);   // prefetch next ids
            const int rem = cnt - e0;
            float4 v0 = __ldg(x4 + (size_t)cur.x * 16 + j);
            float4 v1, v2, v3;
            if (rem > 1) v1 = __ldg(x4 + (size_t)cur.y * 16 + j);
            if (rem > 2) v2 = __ldg(x4 + (size_t)cur.z * 16 + j);
            if (rem > 3) v3 = __ldg(x4 + (size_t)cur.w * 16 + j);
            acc.x += v0.x; acc.y += v0.y; acc.z += v0.z; acc.w += v0.w;
            if (rem > 1) { acc.x += v1.x; acc.y += v1.y; acc.z += v1.z; acc.w += v1.w; }
            if (rem > 2) { acc.x += v2.x; acc.y += v2.y; acc.z += v2.z; acc.w += v2.w; }
            if (rem > 3) { acc.x += v3.x; acc.y += v3.y; acc.z += v3.z; acc.w += v3.w; }
        }
    } else {
        // overflow fallback (~never): rescan full edge list for this node
        for (int e = 0; e < N_EDGES; e++) {
            if (__ldg(ei + N_EDGES + e) == node) {
                float4 v = __ldg(x4 + (size_t)__ldg(ei + e) * 16 + j);
                acc.x += v.x; acc.y += v.y; acc.z += v.z; acc.w += v.w;
            }
        }
    }
    acc.x *= r; acc.y *= r; acc.z *= r; acc.w *= r;
    reinterpret_cast<float4*>(g_mean)[(size_t)node * 16 + j] = acc;
}

// ---------------------------------------------------------------------------
// Kernel 4: out = relu(mean @ Wl^T + b + x @ Wr^T)
// Block: 128 nodes x 64 outputs. 256 threads, each 8 nodes x 4 outputs.
// Packed f32x2 FMA accumulation (2 nodes per 64-bit register).
// ---------------------------------------------------------------------------
#define WPAD 68
#define APAD 132

__global__ __launch_bounds__(256) void out_kernel(
    const float* __restrict__ x,
    const float* __restrict__ Wl,
    const float* __restrict__ bl,
    const float* __restrict__ Wr,
    float* __restrict__ out)
{
    extern __shared__ float sm[];
    float* sWl = sm;                        // [64][WPAD] k-major
    float* sWr = sWl + D * WPAD;            // [64][WPAD]
    float* sA  = sWr + D * WPAD;            // [64][APAD] mean, k-major
    float* sX  = sA  + D * APAD;            // [64][APAD] x, k-major
    float* sB  = sX  + D * APAD;            // [64]

    const int tid = threadIdx.x;
    const int tx  = tid & 15;
    const int ty  = tid >> 4;
    const int node0 = blockIdx.x * 128;

    for (int t = tid; t < 1024; t += 256) {
        const int o = t >> 4, k = (t & 15) * 4;
        float4 w = __ldg(reinterpret_cast<const float4*>(Wl) + t);
        sWl[(k+0)*WPAD+o]=w.x; sWl[(k+1)*WPAD+o]=w.y;
        sWl[(k+2)*WPAD+o]=w.z; sWl[(k+3)*WPAD+o]=w.w;
        float4 u = __ldg(reinterpret_cast<const float4*>(Wr) + t);
        sWr[(k+0)*WPAD+o]=u.x; sWr[(k+1)*WPAD+o]=u.y;
        sWr[(k+2)*WPAD+o]=u.z; sWr[(k+3)*WPAD+o]=u.w;
    }
    if (tid < D) sB[tid] = __ldg(bl + tid);
    __syncthreads();

    for (int t = tid; t < 2048; t += 256) {
        const int node = t >> 4, kq = t & 15, k = kq * 4;
        const int gn = node0 + node;
        float4 a  = make_float4(0.f,0.f,0.f,0.f);
        float4 xv = a;
        if (gn < N_NODES) {
            a  = __ldg(reinterpret_cast<const float4*>(g_mean) + (size_t)gn*16 + kq);
            xv = __ldg(reinterpret_cast<const float4*>(x)      + (size_t)gn*16 + kq);
        }
        sA[(k+0)*APAD+node]=a.x; sA[(k+1)*APAD+node]=a.y;
        sA[(k+2)*APAD+node]=a.z; sA[(k+3)*APAD+node]=a.w;
        sX[(k+0)*APAD+node]=xv.x; sX[(k+1)*APAD+node]=xv.y;
        sX[(k+2)*APAD+node]=xv.z; sX[(k+3)*APAD+node]=xv.w;
    }
    __syncthreads();

    const int nb = ty * 8;
    const int ob = tx * 4;

    unsigned long long acc[4][4];
    #pragma unroll
    for (int o = 0; o < 4; o++) {
        const float b = sB[ob + o];
        unsigned long long bp;
        asm("mov.b64 %0, {%1, %2};" : "=l"(bp) : "f"(b), "f"(b));
        #pragma unroll
        for (int m = 0; m < 4; m++) acc[m][o] = bp;
    }

    #pragma unroll 8
    for (int k = 0; k < D; k++) {
        const float4 wl4 = *reinterpret_cast<const float4*>(sWl + k*WPAD + ob);
        const float4 wr4 = *reinterpret_cast<const float4*>(sWr + k*WPAD + ob);
        const ulonglong2 aA = *reinterpret_cast<const ulonglong2*>(sA + k*APAD + nb);
        const ulonglong2 aB = *reinterpret_cast<const ulonglong2*>(sA + k*APAD + nb + 4);
        const ulonglong2 xA = *reinterpret_cast<const ulonglong2*>(sX + k*APAD + nb);
        const ulonglong2 xB = *reinterpret_cast<const ulonglong2*>(sX + k*APAD + nb + 4);
        const unsigned long long ap[4] = {aA.x, aA.y, aB.x, aB.y};
        const unsigned long long xp[4] = {xA.x, xA.y, xB.x, xB.y};
        const float wlv[4] = {wl4.x, wl4.y, wl4.z, wl4.w};
        const float wrv[4] = {wr4.x, wr4.y, wr4.z, wr4.w};
        #pragma unroll
        for (int o = 0; o < 4; o++) {
            unsigned long long wl2, wr2;
            asm("mov.b64 %0, {%1, %2};" : "=l"(wl2) : "f"(wlv[o]), "f"(wlv[o]));
            asm("mov.b64 %0, {%1, %2};" : "=l"(wr2) : "f"(wrv[o]), "f"(wrv[o]));
            #pragma unroll
            for (int m = 0; m < 4; m++) {
                asm("fma.rn.f32x2 %0, %1, %2, %0;" : "+l"(acc[m][o]) : "l"(ap[m]), "l"(wl2));
                asm("fma.rn.f32x2 %0, %1, %2, %0;" : "+l"(acc[m][o]) : "l"(xp[m]), "l"(wr2));
            }
        }
    }

    #pragma unroll
    for (int m = 0; m < 4; m++) {
        float lo[4], hi[4];
        #pragma unroll
        for (int o = 0; o < 4; o++)
            asm("mov.b64 {%0, %1}, %2;" : "=f"(lo[o]), "=f"(hi[o]) : "l"(acc[m][o]));
        const int g0 = node0 + nb + m * 2;
        if (g0 < N_NODES) {
            float4 v = make_float4(fmaxf(lo[0],0.f), fmaxf(lo[1],0.f),
                                   fmaxf(lo[2],0.f), fmaxf(lo[3],0.f));
            *reinterpret_cast<float4*>(out + (size_t)g0*D + ob) = v;
        }
        if (g0 + 1 < N_NODES) {
            float4 v = make_float4(fmaxf(hi[0],0.f), fmaxf(hi[1],0.f),
                                   fmaxf(hi[2],0.f), fmaxf(hi[3],0.f));
            *reinterpret_cast<float4*>(out + (size_t)(g0+1)*D + ob) = v;
        }
    }
}

// ---------------------------------------------------------------------------
extern "C" void kernel_launch(void* const* d_in, const int* in_sizes, int n_in,
                              void* d_out, int out_size)
{
    const float* x  = (const float*)d_in[0];
    const int*   ei = (const int*)d_in[1];     // int32 (JAX x64 disabled)
    const float* Wl = (const float*)d_in[2];
    const float* bl = (const float*)d_in[3];
    const float* Wr = (const float*)d_in[4];
    float* out = (float*)d_out;

    const int smem_bytes = (2 * D * WPAD + 2 * D * APAD + D) * sizeof(float);
    cudaFuncSetAttribute(out_kernel, cudaFuncAttributeMaxDynamicSharedMemorySize, smem_bytes);

    zero_kernel<<<(N_NODES + 255) / 256, 256>>>();
    fill_kernel<<<(N_EDGES / 2 + 255) / 256, 256>>>(ei);
    gather_kernel<<<N_NODES / 16, 256>>>(x, ei);   // 2 nodes/warp * 8 warps = 16/block
    out_kernel<<<(N_NODES + 127) / 128, 256, smem_bytes>>>(x, Wl, bl, Wr, out);
}